// round 17
// baseline (speedup 1.0000x reference)
#include <cuda_runtime.h>
#include <cuda_fp16.h>
#include <math.h>

#define B 8
#define N 4096
#define DF 768
#define K1 8
#define K2 2
#define DS 128
#define BK (B*K1)        // 64
#define NS (BK*K2)       // 128 slot rows
#define SCALE 0.088388347648318447f
#define EPS_SA 1e-8f
#define OBJ_SIZE (NS*DS)

// ------------------- scratch (device globals) -------------------
__device__ float g_mean[B*N];
__device__ float g_var[B*N];
__device__ float g_s[BK*N];
__device__ float g_sm[BK];
__device__ __align__(16) float g_T[BK*DF];
__device__ float g_slots[NS*DS];
__device__ __align__(16) float g_aD[BK*DF];
__device__ float g_sAD[BK];
__device__ float g_beD[BK];
__device__ __align__(16) float g_acc0[BK*DF];
__device__ float g_z0[BK];
__device__ float g_d0[BK];
__device__ float g_cv[DS];
__device__ float g_kg[DS];
__device__ float g_kb[DS];
__device__ __align__(16) __half g_tok16[(size_t)B*N*DF];   // fp16 tokens (50MB)
// transposed weights
__device__ float g_WvT[DF*DS];
__device__ float g_WihT[DS*3*DS];
__device__ float g_WhhT[DS*3*DS];
__device__ float g_W1T[DS*4*DS];
__device__ float g_W2T[4*DS*DS];

__device__ __forceinline__ void warp_reduce2(float& x, float& y, int lane) {
    float xo = __shfl_xor_sync(0xffffffffu, x, 16);
    float yo = __shfl_xor_sync(0xffffffffu, y, 16);
    float v  = (lane < 16) ? (x + xo) : (y + yo);
    #pragma unroll
    for (int off = 8; off; off >>= 1) v += __shfl_xor_sync(0xffffffffu, v, off);
    x = __shfl_sync(0xffffffffu, v, 0);
    y = __shfl_sync(0xffffffffu, v, 16);
}

__device__ __forceinline__ float block_reduce_256(float v, float* red, int tid) {
    red[tid] = v; __syncthreads();
    #pragma unroll
    for (int h = 128; h > 0; h >>= 1) {
        if (tid < h) red[tid] += red[tid + h];
        __syncthreads();
    }
    float r = red[0];
    __syncthreads();
    return r;
}

__device__ __forceinline__ float2 h2f(unsigned u) {
    __half2 h; *(unsigned*)&h = u;
    return __half22float2(h);
}

// packed dual-FMA: d += a*b elementwise on float2, via Blackwell fma.rn.f32x2.
__device__ __forceinline__ void fma2(float2& d, float2 a, float2 b) {
    asm("{\n\t"
        ".reg .b64 ra, rb, rd;\n\t"
        "mov.b64 ra, {%2, %3};\n\t"
        "mov.b64 rb, {%4, %5};\n\t"
        "mov.b64 rd, {%0, %1};\n\t"
        "fma.rn.f32x2 rd, ra, rb, rd;\n\t"
        "mov.b64 {%0, %1}, rd;\n\t"
        "}"
        : "+f"(d.x), "+f"(d.y)
        : "f"(a.x), "f"(a.y), "f"(b.x), "f"(b.y));
}

// ------------------- one-time kernels -------------------
// per-token mean/var over DF + fp16 conversion.  grid B*N/8 blocks of 256 (warp/row)
__global__ void stats_kernel(const float* __restrict__ tokens) {
    int row  = blockIdx.x * 8 + (threadIdx.x >> 5);
    int lane = threadIdx.x & 31;
    const float4* xp = (const float4*)(tokens + (size_t)row * DF);
    uint2* hp = (uint2*)(g_tok16 + (size_t)row * DF);
    float s = 0.f, s2 = 0.f;
    #pragma unroll
    for (int k = 0; k < 6; k++) {
        float4 v = xp[k*32 + lane];
        s  += v.x + v.y + v.z + v.w;
        s2 += v.x*v.x + v.y*v.y + v.z*v.z + v.w*v.w;
        __half2 h0 = __floats2half2_rn(v.x, v.y);
        __half2 h1 = __floats2half2_rn(v.z, v.w);
        uint2 u; u.x = *(unsigned*)&h0; u.y = *(unsigned*)&h1;
        hp[k*32 + lane] = u;
    }
    #pragma unroll
    for (int off = 16; off; off >>= 1) {
        s  += __shfl_xor_sync(0xffffffffu, s,  off);
        s2 += __shfl_xor_sync(0xffffffffu, s2, off);
    }
    if (lane == 0) {
        float m = s * (1.f/DF);
        g_mean[row] = m;
        g_var[row]  = s2 * (1.f/DF) - m*m;
    }
}

// fused denom + s; blocks 0-31 additionally compute kg/kb.  grid BK blocks of 256
__global__ void dss_kernel(const float* __restrict__ masks, const float* __restrict__ Wk,
                           const float* __restrict__ ig, const float* __restrict__ ib) {
    __shared__ float red[256];
    int bk = blockIdx.x, b = bk >> 3, tid = threadIdx.x;
    float s = 0.f;
    for (int j = tid; j < N; j += 256) s += masks[(size_t)bk*N + j];
    float denom = block_reduce_256(s, red, tid) * (1.f/N);
    int good = denom > 1e-6f;
    float inv = 1.f / (denom + 1e-6f);
    for (int j = tid; j < N; j += 256) {
        float w = good ? masks[(size_t)bk*N + j] * inv : 1.0f;
        float v = g_var[b*N + j];
        g_s[(size_t)bk*N + j] = w * rsqrtf(w*w*v + 1e-5f);
    }
    if (bk < 32) {
        int w = tid >> 5, lane = tid & 31;
        int c = (bk & 15)*8 + w;
        const float* vv = (bk < 16) ? ig : ib;
        float acc = 0.f;
        #pragma unroll
        for (int k = 0; k < 24; k++) {
            int f = k*32 + lane;
            acc += Wk[(size_t)c*DF + f] * vv[f];
        }
        #pragma unroll
        for (int off = 16; off; off >>= 1) acc += __shfl_xor_sync(0xffffffffu, acc, off);
        if (lane == 0) { if (bk < 16) g_kg[c] = acc; else g_kb[c] = acc; }
    }
}

// transpose weight matrices (Wv, Wih, Whh, W1, W2)
__global__ void tr_kernel(const float* __restrict__ Wv,
                          const float* __restrict__ Wih, const float* __restrict__ Whh,
                          const float* __restrict__ W1, const float* __restrict__ W2) {
    int i = blockIdx.x*256 + threadIdx.x;
    if (i < DF*DS) { int f = i/DS, o = i%DS; g_WvT[i] = Wv[o*DF + f]; return; }
    i -= DF*DS;
    if (i < DS*3*DS) { int f = i/(3*DS), o = i%(3*DS); g_WihT[i] = Wih[o*DS + f]; return; }
    i -= DS*3*DS;
    if (i < DS*3*DS) { int f = i/(3*DS), o = i%(3*DS); g_WhhT[i] = Whh[o*DS + f]; return; }
    i -= DS*3*DS;
    if (i < DS*4*DS) { int f = i/(4*DS), o = i%(4*DS); g_W1T[i] = W1[o*DS + f]; return; }
    i -= DS*4*DS;
    if (i < 4*DS*DS) { int o = i/DS, t = i%DS; g_W2T[i] = W2[t*4*DS + o]; return; }
}

// cv = Wv @ ln_in_b.  grid 16 blocks x 256 (warp per output col)
__global__ void cv_kernel(const float* __restrict__ Wv, const float* __restrict__ lnb) {
    int col  = blockIdx.x*8 + (threadIdx.x >> 5);
    int lane = threadIdx.x & 31;
    float a = 0.f;
    #pragma unroll
    for (int k = 0; k < 24; k++) {
        int f = k*32 + lane;
        a += Wv[(size_t)col*DF + f] * lnb[f];
    }
    #pragma unroll
    for (int off = 16; off; off >>= 1) a += __shfl_xor_sync(0xffffffffu, a, off);
    if (lane == 0) g_cv[col] = a;
}

// ------------------- per-iteration kernels -------------------
// grid = BK*3 blocks: (bk, ff-slice).
__global__ void qa_kernel(const float* __restrict__ ps, const float* __restrict__ eps,
                          const float* __restrict__ Wq, const float* __restrict__ Wk,
                          const float* __restrict__ sg, const float* __restrict__ sb,
                          const float* __restrict__ ig, const float* __restrict__ ib,
                          int first) {
    __shared__ float sn[2][DS], qsh[2][DS], qD[DS], red[256];
    int bk = blockIdx.x / 3, ff = blockIdx.x % 3;
    int tid = threadIdx.x;
    int half = tid >> 7, t = tid & 127;
    int r = bk*2 + half;
    float val;
    if (first) {
        val = ps[bk*DS + t] + 0.01f * eps[r*DS + t];
        if (ff == 0) g_slots[r*DS + t] = val;
    } else {
        val = g_slots[r*DS + t];
    }
    red[tid] = val; __syncthreads();
    #pragma unroll
    for (int h = 64; h; h >>= 1) { if (t < h) red[tid] += red[tid + h]; __syncthreads(); }
    float m = red[half*128] * (1.f/DS);
    __syncthreads();
    float dv = val - m;
    red[tid] = dv*dv; __syncthreads();
    #pragma unroll
    for (int h = 64; h; h >>= 1) { if (t < h) red[tid] += red[tid + h]; __syncthreads(); }
    float rstd = rsqrtf(red[half*128] * (1.f/DS) + 1e-5f);
    __syncthreads();
    sn[half][t] = dv * rstd * sg[t] + sb[t];
    __syncthreads();
    {
        float q0 = 0.f, q1 = 0.f;
        #pragma unroll 4
        for (int f = 0; f < DS; f += 2) {
            q0 += Wq[t*DS + f]   * sn[half][f];
            q1 += Wq[t*DS + f+1] * sn[half][f+1];
        }
        qsh[half][t] = q0 + q1;
    }
    __syncthreads();
    if (tid < DS) qD[tid] = qsh[0][tid] - qsh[1][tid];
    __syncthreads();
    {
        int f = ff*256 + tid;
        float r0=0.f, r1=0.f, r2=0.f, r3=0.f;
        #pragma unroll 4
        for (int c = 0; c < DS; c += 4) {
            r0 += Wk[c*DF + f]     * qD[c];
            r1 += Wk[(c+1)*DF + f] * qD[c+1];
            r2 += Wk[(c+2)*DF + f] * qD[c+2];
            r3 += Wk[(c+3)*DF + f] * qD[c+3];
        }
        float raw = (r0+r1)+(r2+r3);
        g_aD[(size_t)bk*DF + f]   = raw * ig[f];
        g_acc0[(size_t)bk*DF + f] = 0.f;
        if (first) g_T[(size_t)bk*DF + f] = 0.f;
    }
    if (ff == 0) {
        float psm = (tid < DS) ? qD[tid]*g_kg[tid] : 0.f;
        float pbe = (tid < DS) ? qD[tid]*g_kb[tid] : 0.f;
        float ts = block_reduce_256(psm, red, tid);
        float tb = block_reduce_256(pbe, red, tid);
        if (tid == 0) {
            g_sAD[bk] = ts; g_beD[bk] = tb;
            g_z0[bk] = 0.f; g_d0[bk] = 0.f;
            if (first) g_sm[bk] = 0.f;
        }
    }
}

// Phased big kernel, fp16 tokens, double-buffered smem, packed f32x2 FMA.
// block = 256, pair of bks, 4 chunks of 32 tokens; one barrier per chunk.
__global__ void __launch_bounds__(256, 2) big_kernel(const float* __restrict__ masks,
                                                     float* __restrict__ out,
                                                     int first, int last) {
    extern __shared__ uint4 xs4[];               // 2 buffers of 32*97 uint4
    float* dtp = (float*)(xs4 + 2*32*97);        // 2 buffers of 64 floats

    int p = blockIdx.x & 31, tile = blockIdx.x >> 5;
    int bk0 = 2*p, bk1 = bk0 + 1, b = p >> 2;
    int tid = threadIdx.x, w = tid >> 5, lane = tid & 31;

    const float2* a0p = (const float2*)(g_aD + (size_t)bk0*DF);
    const float2* a1p = (const float2*)(g_aD + (size_t)bk1*DF);
    float2 a0v[12], a1v[12];
    #pragma unroll
    for (int kk = 0; kk < 3; kk++) {
        #pragma unroll
        for (int h = 0; h < 4; h++) {
            a0v[kk*4+h] = a0p[(kk*32 + lane)*4 + h];
            a1v[kk*4+h] = a1p[(kk*32 + lane)*4 + h];
        }
    }
    float sA0 = g_sAD[bk0], sA1 = g_sAD[bk1];
    float be0 = g_beD[bk0], be1 = g_beD[bk1];
    float2 acc0a = {0,0}, acc0b = {0,0}, acc1a = {0,0}, acc1b = {0,0};
    float2 accT0a = {0,0}, accT0b = {0,0}, accT1a = {0,0}, accT1b = {0,0};
    float z0=0.f, z1=0.f, dd0=0.f, dd1=0.f, sm0=0.f, sm1=0.f;

    auto stageA = [&](int cc) {
        int j0 = tile*128 + cc*32;
        uint4* xb = xs4 + (cc & 1)*(32*97);
        float* dt = dtp + (cc & 1)*64;
        #pragma unroll
        for (int u = 0; u < 4; u++) {
            int t = w*4 + u;
            const uint4* gx = (const uint4*)(g_tok16 + (size_t)(b*N + j0 + t)*DF);
            float2 d0p = {0,0}, d1p = {0,0};
            #pragma unroll
            for (int kk = 0; kk < 3; kk++) {
                uint4 xq = gx[kk*32 + lane];
                xb[t*97 + kk*32 + lane] = xq;
                float2 x0 = h2f(xq.x), x1 = h2f(xq.y), x2 = h2f(xq.z), x3 = h2f(xq.w);
                fma2(d0p, a0v[kk*4+0], x0); fma2(d0p, a0v[kk*4+1], x1);
                fma2(d0p, a0v[kk*4+2], x2); fma2(d0p, a0v[kk*4+3], x3);
                fma2(d1p, a1v[kk*4+0], x0); fma2(d1p, a1v[kk*4+1], x1);
                fma2(d1p, a1v[kk*4+2], x2); fma2(d1p, a1v[kk*4+3], x3);
            }
            float d0 = d0p.x + d0p.y, d1 = d1p.x + d1p.y;
            warp_reduce2(d0, d1, lane);
            if (lane == 0) { dt[t] = d0; dt[32 + t] = d1; }
        }
    };

    stageA(0);
    __syncthreads();

    for (int cc = 0; cc < 4; cc++) {
        int j0 = tile*128 + cc*32;
        float* dt = dtp + (cc & 1)*64;
        int j = j0 + lane;
        float d0 = dt[lane], d1 = dt[32 + lane];
        float s0 = g_s[(size_t)bk0*N + j], s1 = g_s[(size_t)bk1*N + j];
        float m  = g_mean[b*N + j];
        float p0 = 1.f/(1.f + __expf(-(SCALE*(s0*(d0 - m*sA0) + be0))));
        float p1 = 1.f/(1.f + __expf(-(SCALE*(s1*(d1 - m*sA1) + be1))));
        float at0 = p0 + EPS_SA, at1 = p1 + EPS_SA;
        float c0 = at0*s0, c1 = at1*s1;
        if (w == 0) {
            z0 += at0; z1 += at1; dd0 += c0*m; dd1 += c1*m;
            if (first) { sm0 += s0*m; sm1 += s1*m; }
            if (last) {
                float mk0 = masks[(size_t)bk0*N + j];
                float mk1 = masks[(size_t)bk1*N + j];
                out[OBJ_SIZE + (size_t)(bk0*2)*N + j]   = at0*mk0;
                out[OBJ_SIZE + (size_t)(bk0*2+1)*N + j] = (1.f - p0 + EPS_SA)*mk0;
                out[OBJ_SIZE + (size_t)(bk1*2)*N + j]   = at1*mk1;
                out[OBJ_SIZE + (size_t)(bk1*2+1)*N + j] = (1.f - p1 + EPS_SA)*mk1;
            }
        }
        if (tid < 192) {
            const uint2* xs2 = (const uint2*)(xs4 + (cc & 1)*(32*97));
            if (first) {
                #pragma unroll
                for (int t = 0; t < 32; t++) {
                    uint2 xq = xs2[t*194 + tid];
                    float2 xa = h2f(xq.x), xb2 = h2f(xq.y);
                    float c0t = __shfl_sync(0xffffffffu, c0, t);
                    float c1t = __shfl_sync(0xffffffffu, c1, t);
                    float s0t = __shfl_sync(0xffffffffu, s0, t);
                    float s1t = __shfl_sync(0xffffffffu, s1, t);
                    float2 pc0 = {c0t, c0t}, pc1 = {c1t, c1t};
                    float2 ps0 = {s0t, s0t}, ps1 = {s1t, s1t};
                    fma2(acc0a, pc0, xa); fma2(acc0b, pc0, xb2);
                    fma2(acc1a, pc1, xa); fma2(acc1b, pc1, xb2);
                    fma2(accT0a, ps0, xa); fma2(accT0b, ps0, xb2);
                    fma2(accT1a, ps1, xa); fma2(accT1b, ps1, xb2);
                }
            } else {
                #pragma unroll
                for (int t = 0; t < 32; t++) {
                    uint2 xq = xs2[t*194 + tid];
                    float2 xa = h2f(xq.x), xb2 = h2f(xq.y);
                    float c0t = __shfl_sync(0xffffffffu, c0, t);
                    float c1t = __shfl_sync(0xffffffffu, c1, t);
                    float2 pc0 = {c0t, c0t}, pc1 = {c1t, c1t};
                    fma2(acc0a, pc0, xa); fma2(acc0b, pc0, xb2);
                    fma2(acc1a, pc1, xa); fma2(acc1b, pc1, xb2);
                }
            }
        }
        if (cc < 3) stageA(cc + 1);
        __syncthreads();
    }

    if (tid < 192) {
        size_t f0 = (size_t)bk0*DF + tid*4;
        size_t f1 = (size_t)bk1*DF + tid*4;
        atomicAdd(&g_acc0[f0+0], acc0a.x); atomicAdd(&g_acc0[f0+1], acc0a.y);
        atomicAdd(&g_acc0[f0+2], acc0b.x); atomicAdd(&g_acc0[f0+3], acc0b.y);
        atomicAdd(&g_acc0[f1+0], acc1a.x); atomicAdd(&g_acc0[f1+1], acc1a.y);
        atomicAdd(&g_acc0[f1+2], acc1b.x); atomicAdd(&g_acc0[f1+3], acc1b.y);
        if (first) {
            atomicAdd(&g_T[f0+0], accT0a.x); atomicAdd(&g_T[f0+1], accT0a.y);
            atomicAdd(&g_T[f0+2], accT0b.x); atomicAdd(&g_T[f0+3], accT0b.y);
            atomicAdd(&g_T[f1+0], accT1a.x); atomicAdd(&g_T[f1+1], accT1a.y);
            atomicAdd(&g_T[f1+2], accT1b.x); atomicAdd(&g_T[f1+3], accT1b.y);
        }
    }
    if (w == 0) {
        warp_reduce2(z0, z1, lane);
        warp_reduce2(dd0, dd1, lane);
        if (first) warp_reduce2(sm0, sm1, lane);
        if (lane == 0) {
            atomicAdd(&g_z0[bk0], z0);  atomicAdd(&g_z0[bk1], z1);
            atomicAdd(&g_d0[bk0], dd0); atomicAdd(&g_d0[bk1], dd1);
            if (first) { atomicAdd(&g_sm[bk0], sm0); atomicAdd(&g_sm[bk1], sm1); }
        }
    }
}

// upd v4: 4 slot rows per block (32 blocks x 512 thr); thread = (row, col).
// Weights streamed once per block and reused across 4 rows; no partial reductions.
__global__ void __launch_bounds__(512) upd_kernel(const float* __restrict__ ig,
                           const float* __restrict__ bih, const float* __restrict__ bhh,
                           const float* __restrict__ mg,  const float* __restrict__ mb,
                           const float* __restrict__ b1,  const float* __restrict__ b2,
                           float* __restrict__ out, int last) {
    __shared__ float gv[4][DF];        // 12KB
    __shared__ float sh[4][DS], su[4][DS], shh[4][DS];
    __shared__ float sy[4][4*DS];      // 8KB
    __shared__ float red[4][DS];       // 2KB
    int r0 = blockIdx.x * 4;
    int tid = threadIdx.x;
    int col = tid & 127, row = tid >> 7;      // row 0..3
    int r = r0 + row;
    const float ONE = 1.f + 2.f*EPS_SA;

    // load gv for all 4 rows (grid-stride over f per row)
    #pragma unroll
    for (int rr = 0; rr < 4; rr++) {
        int rrr = r0 + rr, bkr = rrr >> 1, ii = rrr & 1;
        float D0 = g_d0[bkr];
        float D = ii ? (g_sm[bkr]*ONE - D0) : D0;
        for (int f = tid; f < DF; f += 512) {
            float A = g_acc0[(size_t)bkr*DF + f];
            if (ii) A = g_T[(size_t)bkr*DF + f]*ONE - A;
            gv[rr][f] = ig[f] * (A - D);
        }
    }
    if (tid < 4*DS) sh[tid >> 7][tid & 127] = g_slots[(size_t)r0*DS + tid];
    __syncthreads();

    // Wv matvec: thread (row,col), full 768-f loop, weights shared across rows via L1
    float Zr;
    {
        int bkr = r >> 1, ii = r & 1;
        float Z0 = g_z0[bkr];
        Zr = ii ? (4096.f*ONE - Z0) : Z0;
        float a0=0.f,a1=0.f,a2=0.f,a3=0.f;
        #pragma unroll 4
        for (int f = 0; f < DF; f += 4) {
            a0 += g_WvT[(f+0)*DS + col] * gv[row][f+0];
            a1 += g_WvT[(f+1)*DS + col] * gv[row][f+1];
            a2 += g_WvT[(f+2)*DS + col] * gv[row][f+2];
            a3 += g_WvT[(f+3)*DS + col] * gv[row][f+3];
        }
        su[row][col] = ((a0+a1)+(a2+a3)) / Zr + g_cv[col];
    }
    __syncthreads();

    // GRU: thread (row,col) computes all 6 gates over full 128-f range
    float news;
    {
        float gi0 = bih[col], gi1 = bih[DS+col], gi2 = bih[2*DS+col];
        float gh0 = bhh[col], gh1 = bhh[DS+col], gh2 = bhh[2*DS+col];
        #pragma unroll 4
        for (int f = 0; f < DS; f++) {
            float uf = su[row][f], hf = sh[row][f];
            gi0 += g_WihT[f*(3*DS) + col]*uf;
            gi1 += g_WihT[f*(3*DS) + DS + col]*uf;
            gi2 += g_WihT[f*(3*DS) + 2*DS + col]*uf;
            gh0 += g_WhhT[f*(3*DS) + col]*hf;
            gh1 += g_WhhT[f*(3*DS) + DS + col]*hf;
            gh2 += g_WhhT[f*(3*DS) + 2*DS + col]*hf;
        }
        float rr2 = 1.f / (1.f + __expf(-(gi0 + gh0)));
        float zz = 1.f / (1.f + __expf(-(gi1 + gh1)));
        float nn = tanhf(gi2 + rr2*gh2);
        news = (1.f - zz)*nn + zz*sh[row][col];
    }
    // LN per row (reduction within each row's 128 threads)
    red[row][col] = news;
    __syncthreads();
    #pragma unroll
    for (int h2 = 64; h2; h2 >>= 1) {
        if (col < h2) red[row][col] += red[row][col + h2];
        __syncthreads();
    }
    float m = red[row][0] * (1.f/DS);
    __syncthreads();
    float dv = news - m;
    red[row][col] = dv*dv;
    __syncthreads();
    #pragma unroll
    for (int h2 = 64; h2; h2 >>= 1) {
        if (col < h2) red[row][col] += red[row][col + h2];
        __syncthreads();
    }
    float rstd = rsqrtf(red[row][0]*(1.f/DS) + 1e-5f);
    shh[row][col] = dv*rstd*mg[col] + mb[col];
    __syncthreads();

    // MLP W1: thread owns output o = tid for ALL 4 rows (weight loaded once)
    {
        float aa0 = b1[tid], aa1 = aa0, aa2 = aa0, aa3 = aa0;
        #pragma unroll 4
        for (int f = 0; f < DS; f++) {
            float w = g_W1T[f*(4*DS) + tid];
            aa0 += w * shh[0][f];
            aa1 += w * shh[1][f];
            aa2 += w * shh[2][f];
            aa3 += w * shh[3][f];
        }
        sy[0][tid] = 0.5f * aa0 * (1.f + erff(aa0 * 0.70710678118654752f));
        sy[1][tid] = 0.5f * aa1 * (1.f + erff(aa1 * 0.70710678118654752f));
        sy[2][tid] = 0.5f * aa2 * (1.f + erff(aa2 * 0.70710678118654752f));
        sy[3][tid] = 0.5f * aa3 * (1.f + erff(aa3 * 0.70710678118654752f));
    }
    __syncthreads();

    // W2: thread (row,col), full 512-o loop
    {
        float a0=0.f,a1=0.f,a2=0.f,a3=0.f;
        #pragma unroll 4
        for (int o = 0; o < 4*DS; o += 4) {
            a0 += g_W2T[(o+0)*DS + col]*sy[row][o+0];
            a1 += g_W2T[(o+1)*DS + col]*sy[row][o+1];
            a2 += g_W2T[(o+2)*DS + col]*sy[row][o+2];
            a3 += g_W2T[(o+3)*DS + col]*sy[row][o+3];
        }
        float o2 = b2[col] + (a0+a1)+(a2+a3);
        g_slots[(size_t)r*DS + col] = o2;
        if (last) out[(size_t)r*DS + col] = o2;
    }
}

// ------------------- launch -------------------
#define BIG_SMEM (2*32*97*16 + 2*64*4)   // 99840 bytes

extern "C" void kernel_launch(void* const* d_in, const int* in_sizes, int n_in,
                              void* d_out, int out_size) {
    const float* tokens = (const float*)d_in[0];
    const float* pslots = (const float*)d_in[1];
    const float* masks  = (const float*)d_in[2];
    const float* eps    = (const float*)d_in[3];
    const float* ig     = (const float*)d_in[4];
    const float* ib     = (const float*)d_in[5];
    const float* sg     = (const float*)d_in[6];
    const float* sb     = (const float*)d_in[7];
    const float* Wq     = (const float*)d_in[8];
    const float* Wk     = (const float*)d_in[9];
    const float* Wv     = (const float*)d_in[10];
    const float* Wih    = (const float*)d_in[11];
    const float* Whh    = (const float*)d_in[12];
    const float* bih    = (const float*)d_in[13];
    const float* bhh    = (const float*)d_in[14];
    const float* mg     = (const float*)d_in[15];
    const float* mb     = (const float*)d_in[16];
    const float* W1     = (const float*)d_in[17];
    const float* b1     = (const float*)d_in[18];
    const float* W2     = (const float*)d_in[19];
    const float* b2     = (const float*)d_in[20];
    float* out = (float*)d_out;

    cudaFuncSetAttribute(big_kernel, cudaFuncAttributeMaxDynamicSharedMemorySize, BIG_SMEM);

    stats_kernel<<<B*N/8, 256>>>(tokens);                               // 0
    dss_kernel<<<BK, 256>>>(masks, Wk, ig, ib);                         // 1
    qa_kernel<<<BK*3, 256>>>(pslots, eps, Wq, Wk, sg, sb, ig, ib, 1);   // 2
    big_kernel<<<32*32, 256, BIG_SMEM>>>(masks, out, 1, 0);             // 3 (profiled)
    tr_kernel<<<(DF*DS + 2*DS*3*DS + 2*DS*4*DS + 255)/256, 256>>>(Wv, Wih, Whh, W1, W2); // 4
    cv_kernel<<<16, 256>>>(Wv, ib);                                     // 5
    upd_kernel<<<NS/4, 512>>>(ig, bih, bhh, mg, mb, b1, b2, out, 0);    // 6

    // iteration 1
    qa_kernel<<<BK*3, 256>>>(pslots, eps, Wq, Wk, sg, sb, ig, ib, 0);
    big_kernel<<<32*32, 256, BIG_SMEM>>>(masks, out, 0, 0);
    upd_kernel<<<NS/4, 512>>>(ig, bih, bhh, mg, mb, b1, b2, out, 0);
    // iteration 2 (last)
    qa_kernel<<<BK*3, 256>>>(pslots, eps, Wq, Wk, sg, sb, ig, ib, 0);
    big_kernel<<<32*32, 256, BIG_SMEM>>>(masks, out, 0, 1);
    upd_kernel<<<NS/4, 512>>>(ig, bih, bhh, mg, mb, b1, b2, out, 1);
}